// round 5
// baseline (speedup 1.0000x reference)
#include <cuda_runtime.h>

// ---------------- problem constants ----------------
#define NBLK 128
#define NTHR 256
#define LPn  128
#define LQn  128
#define Bn   64
#define Hn   150

// ---------------- device scratch ----------------
__device__ float d_wup[LPn * Bn * Hn];   // [i][b][h]
__device__ float d_Wuq[Bn * LQn * Hn];   // [b][l][h]
__device__ float d_Uqt[Bn * LQn * Hn];   // [b][l][d]
__device__ float d_WgU[600 * 150];
__device__ float d_WgC[600 * 150];
__device__ float d_cc[Bn * 150];
__device__ float d_rg[Bn * 600];
__device__ float d_gh[Bn * 450];
__device__ float d_v[Bn * 150];
__device__ unsigned long long g_arrive;
__device__ unsigned long long g_release;

// ---------------- smem layout (floats) ----------------
#define BUF_OFF   0
#define BUF_SZ    20000     // aliased scratch per phase
#define US_OFF    (BUF_OFF + 10000)     // u_s lives in upper half of BUF
#define WGU_OFF   (BUF_OFF + BUF_SZ)    // 5 rows x 152 (f4-padded)
#define WGC_OFF   (WGU_OFF + 760)
#define WIH_OFF   (WGC_OFF + 760)       // 9 x 600
#define W2_OFF    (WIH_OFF + 5400)      // 22650: P1 scratch | WUQ(19200)+VB(152) | WHH(1200)
#define SMEM_FL   (W2_OFF + 22650)      // 49570 floats
#define SMEM_BYTES (SMEM_FL * 4)        // 198280 B

// ---------------- helpers ----------------
__device__ __forceinline__ float warp_sum(float v) {
#pragma unroll
    for (int o = 16; o > 0; o >>= 1) v += __shfl_down_sync(0xffffffffu, v, o);
    return v;
}
__device__ __forceinline__ float warp_max_all(float v) {
#pragma unroll
    for (int o = 16; o > 0; o >>= 1) v = fmaxf(v, __shfl_xor_sync(0xffffffffu, v, o));
    return v;
}
__device__ __forceinline__ float warp_sum_all(float v) {
#pragma unroll
    for (int o = 16; o > 0; o >>= 1) v += __shfl_xor_sync(0xffffffffu, v, o);
    return v;
}
__device__ __forceinline__ float fast_sig(float x) {
    return 1.0f / (1.0f + __expf(-x));
}
__device__ __forceinline__ float fast_tanh(float x) {   // precise path (GRU)
    float cx = fminf(fmaxf(x, -15.0f), 15.0f);
    float e  = __expf(2.0f * cx);
    return __fdividef(e - 1.0f, e + 1.0f);
}
__device__ __forceinline__ float tanh_fastest(float x) { // attention path
    float y;
    asm("tanh.approx.f32 %0, %1;" : "=f"(y) : "f"(x));
    return y;
}

// Grid barrier: monotonic counters; tight acquire spin (no nanosleep).
// The __threadfence() pair is load-bearing: gpu-scope fence -> CCTL.IVALL ->
// block-wide L1D invalidate so post-barrier reads see fresh L2 data.
__device__ __forceinline__ void gsync(unsigned long long& gen) {
    __syncthreads();
    if (threadIdx.x == 0) {
        unsigned long long target = ++gen;
        __threadfence();
        unsigned long long t = atomicAdd(&g_arrive, 1ULL);
        if (t == target * (unsigned long long)NBLK - 1ULL) {
            atomicExch(&g_release, target);
        } else {
            unsigned long long r;
            do {
                asm volatile("ld.acquire.gpu.u64 %0, [%1];"
                             : "=l"(r) : "l"(&g_release) : "memory");
            } while (r < target);
        }
        __threadfence();
    }
    __syncthreads();
}

// ---------------- the persistent kernel ----------------
__global__ void __launch_bounds__(NTHR, 1) pqm_kernel(
    const float* __restrict__ Up, const float* __restrict__ Uq,
    const float* __restrict__ Wp, const float* __restrict__ Wq,
    const float* __restrict__ Wv, const float* __restrict__ Wg,
    const float* __restrict__ Vmat, const float* __restrict__ v0,
    const float* __restrict__ W_ih, const float* __restrict__ W_hh,
    const float* __restrict__ b_ih, const float* __restrict__ b_hh,
    float* __restrict__ out)
{
    extern __shared__ float sm[];
    const int tid = threadIdx.x;
    const int blk = blockIdx.x;

    unsigned long long gen = 0;
    if (tid == 0) gen = *((volatile unsigned long long*)&g_release);

    // ======== P0: fold Wg; copy v0 ========
    for (int idx = blk * NTHR + tid; idx < 600 * 150; idx += NBLK * NTHR) {
        int j = idx / 150, k = idx - j * 150;
        d_WgU[idx] = Wg[j * 600 + k]       + Wg[j * 600 + 150 + k];
        d_WgC[idx] = Wg[j * 600 + 300 + k] + Wg[j * 600 + 450 + k];
    }
    for (int idx = blk * NTHR + tid; idx < Bn * 150; idx += NBLK * NTHR)
        d_v[idx] = v0[idx];
    gsync(gen);

    // ======== P1: hoist wup, Wuq (relayout), Uqt transpose ========
    {
        float* we   = sm + W2_OFF;     // 150*151 scratch
        float* rowb = sm + BUF_OFF;    // 4*152
        const int m = blk;
        for (int idx = tid; idx < 150 * 150; idx += NTHR) {
            int h = idx / 150, d = idx - h * 150;
            we[h * 151 + d] = Wp[h * 300 + d] + Wp[h * 300 + 150 + d];
        }
        __syncthreads();
        for (int b0 = 0; b0 < Bn; b0 += 4) {
            for (int idx = tid; idx < 600; idx += NTHR) {
                int j = idx / 150, d = idx - j * 150;
                rowb[j * 152 + d] = Up[(m * Bn + b0 + j) * 150 + d];
            }
            __syncthreads();
            if (tid < 150) {
                float a0 = 0.f, a1 = 0.f, a2 = 0.f, a3 = 0.f;
                const float* wr = we + tid * 151;
#pragma unroll 6
                for (int k = 0; k < 150; k++) {
                    float w = wr[k];
                    a0 += w * rowb[k];       a1 += w * rowb[152 + k];
                    a2 += w * rowb[304 + k]; a3 += w * rowb[456 + k];
                }
                d_wup[(m * Bn + b0 + 0) * 150 + tid] = a0;
                d_wup[(m * Bn + b0 + 1) * 150 + tid] = a1;
                d_wup[(m * Bn + b0 + 2) * 150 + tid] = a2;
                d_wup[(m * Bn + b0 + 3) * 150 + tid] = a3;
            }
            __syncthreads();
        }
        for (int idx = tid; idx < 150 * 150; idx += NTHR) {
            int h = idx / 150, d = idx - h * 150;
            we[h * 151 + d] = Wq[h * 300 + d] + Wq[h * 300 + 150 + d];
        }
        __syncthreads();
        for (int b0 = 0; b0 < Bn; b0 += 4) {
            for (int idx = tid; idx < 600; idx += NTHR) {
                int j = idx / 150, d = idx - j * 150;
                float vv = Uq[(m * Bn + b0 + j) * 150 + d];
                rowb[j * 152 + d] = vv;
                d_Uqt[((b0 + j) * LQn + m) * 150 + d] = vv;
            }
            __syncthreads();
            if (tid < 150) {
                float a0 = 0.f, a1 = 0.f, a2 = 0.f, a3 = 0.f;
                const float* wr = we + tid * 151;
#pragma unroll 6
                for (int k = 0; k < 150; k++) {
                    float w = wr[k];
                    a0 += w * rowb[k];       a1 += w * rowb[152 + k];
                    a2 += w * rowb[304 + k]; a3 += w * rowb[456 + k];
                }
                d_Wuq[((b0 + 0) * LQn + m) * 150 + tid] = a0;
                d_Wuq[((b0 + 1) * LQn + m) * 150 + tid] = a1;
                d_Wuq[((b0 + 2) * LQn + m) * 150 + tid] = a2;
                d_Wuq[((b0 + 3) * LQn + m) * 150 + tid] = a3;
            }
            __syncthreads();
        }
    }
    gsync(gen);   // d_Wuq/d_Uqt complete before persistent loads

    // ======== persistent smem weight slices ========
    {
        // Phase B slice (f4-padded rows of 152)
        int j0b = (blk * 600) >> 7, nrb = (((blk + 1) * 600) >> 7) - j0b;
        for (int idx = tid; idx < nrb * 152; idx += NTHR) {
            int r = idx / 152, k = idx - r * 152;
            float vu = (k < 150) ? d_WgU[(j0b + r) * 150 + k] : 0.f;
            float vc = (k < 150) ? d_WgC[(j0b + r) * 150 + k] : 0.f;
            sm[WGU_OFF + r * 152 + k] = vu;
            sm[WGC_OFF + r * 152 + k] = vc;
        }
        // Phase C slice (row order o = t*3+g)
        int hb = blk >> 1;
        int nt = (hb < 22) ? 3 : 2;
        for (int idx = tid; idx < nt * 3 * 600; idx += NTHR) {
            int o = idx / 600, k = idx - o * 600;
            int t = o / 3, g = o - 3 * t;
            int j = g * 150 + hb + 64 * t;
            sm[WIH_OFF + idx] = W_ih[j * 600 + k];
        }
        if (blk >= Bn) {  // gh slice
            int bk = blk - Bn;
            int j0g = (bk * 450) >> 6, nrg = (((bk + 1) * 450) >> 6) - j0g;
            for (int idx = tid; idx < nrg * 150; idx += NTHR) {
                int r = idx / 150, k = idx - r * 150;
                sm[W2_OFF + idx] = W_hh[(j0g + r) * 150 + k];
            }
        } else {          // Wuq slice (loop-invariant!) + V row
            const float* src = d_Wuq + blk * (LQn * 150);
            for (int idx = tid; idx < LQn * 150; idx += NTHR)
                sm[W2_OFF + idx] = src[idx];
            if (tid < 150) sm[W2_OFF + 19200 + tid] = Vmat[blk * 150 + tid];
        }
    }
    gsync(gen);

    const int w  = tid >> 5, ln = tid & 31;

    // ======== main scan ========
    for (int i = 0; i < LPn; i++) {
        // ---------- Phase A ----------
        if (blk < Bn) {
            const int b = blk;
            float* v_s  = sm + BUF_OFF;          // 150 (pad 152)
            float* bse  = sm + BUF_OFF + 152;    // 150 (pad 152)
            float* a_s  = sm + BUF_OFF + 304;    // 128
            float* part = sm + BUF_OFF + 432;    // 8*152
            const float* smWuq = sm + W2_OFF;
            const float* Vb    = sm + W2_OFF + 19200;
            if (tid < 150) {
                v_s[tid] = d_v[b * 150 + tid];
                bse[tid] = d_wup[(i * Bn + b) * 150 + tid];
            }
            __syncthreads();
            // bse[h] += (v @ Wv^T)[h]  -- warp per row-pair, global Wv (L2-hot)
            {
                const int w19 = w * 19;
                for (int it = 0; it < 19; it += 2) {
                    int h0 = w19 + it, h1 = h0 + 1;
                    bool has0 = (h0 < 150);
                    bool has1 = (it + 1 < 19) && (h1 < 150);
                    float p0 = 0.f, p1 = 0.f;
                    if (has0) {
                        const float* r0 = Wv + h0 * 150;
                        const float* r1 = Wv + (has1 ? h1 : h0) * 150;
#pragma unroll
                        for (int j = 0; j < 5; j++) {
                            int k = ln + 32 * j;
                            if (k < 150) {
                                float vv = v_s[k];
                                p0 += r0[k] * vv;
                                if (has1) p1 += r1[k] * vv;
                            }
                        }
                    }
                    p0 = warp_sum(p0); p1 = warp_sum(p1);
                    if (ln == 0 && has0) bse[h0] += p0;
                    if (ln == 0 && has1) bse[h1] += p1;
                }
            }
            __syncthreads();
            // s[l]: warp-per-l, Wuq from smem
#pragma unroll 2
            for (int t = 0; t < 16; t++) {
                int l = w * 16 + t;
                const float* wq = smWuq + l * 150;
                float p = 0.f;
#pragma unroll
                for (int k = ln; k < 150; k += 32)
                    p += tanh_fastest(bse[k] + wq[k]) * Vb[k];
                p = warp_sum(p);
                if (ln == 0) a_s[l] = p;
            }
            __syncthreads();
            if (w == 0) {   // softmax
                float a0 = a_s[ln], a1 = a_s[ln + 32], a2 = a_s[ln + 64], a3 = a_s[ln + 96];
                float m = fmaxf(fmaxf(a0, a1), fmaxf(a2, a3));
                m = warp_max_all(m);
                float e0 = __expf(a0 - m), e1 = __expf(a1 - m);
                float e2 = __expf(a2 - m), e3 = __expf(a3 - m);
                float ssum = warp_sum_all(e0 + e1 + e2 + e3);
                float inv = __fdividef(1.0f, ssum);
                a_s[ln] = e0 * inv; a_s[ln + 32] = e1 * inv;
                a_s[ln + 64] = e2 * inv; a_s[ln + 96] = e3 * inv;
            }
            __syncthreads();
            // cc partials: warp w covers l in [16w,16w+16)
#pragma unroll
            for (int p5 = 0; p5 < 5; p5++) {
                int d = ln + 32 * p5;
                if (d < 150) {
                    const float* uq = &d_Uqt[(b * LQn + w * 16) * 150 + d];
                    float acc = 0.f;
#pragma unroll
                    for (int t = 0; t < 16; t++)
                        acc += a_s[w * 16 + t] * uq[t * 150];
                    part[w * 152 + d] = acc;
                }
            }
            __syncthreads();
            if (tid < 150) {
                float acc = 0.f;
#pragma unroll
                for (int w2 = 0; w2 < 8; w2++) acc += part[w2 * 152 + tid];
                d_cc[b * 150 + tid] = acc;
            }
        } else {
            // gh = v @ W_hh^T + b_hh (smem weights)
            const int bk = blk - Bn;
            const int j0 = (bk * 450) >> 6, j1 = ((bk + 1) * 450) >> 6;
            float* v_sp = sm + BUF_OFF;   // 64*151 (<10000, below u_s)
            for (int idx = tid; idx < Bn * 150; idx += NTHR) {
                int b = idx / 150, k = idx - b * 150;
                v_sp[b * 151 + k] = d_v[idx];
            }
            __syncthreads();
            int b = tid & 63, jg = tid >> 6;
            for (int j = j0 + jg; j < j1; j += 4) {
                int jl = j - j0;
                float acc = b_hh[j];
                const float* wr = sm + W2_OFF + jl * 150;
                const float* vr = v_sp + b * 151;
#pragma unroll 10
                for (int k = 0; k < 150; k++) acc += vr[k] * wr[k];
                d_gh[b * 450 + j] = acc;
            }
        }
        // Hoisted Phase-B staging: u_s depends only on Up[i] (not on Phase A).
        {
            __syncthreads();
            float* u_s = sm + US_OFF;           // 64 x 156, f4-padded
            const float* upi = Up + i * Bn * 150;
            for (int idx = tid; idx < Bn * 150; idx += NTHR) {
                int b = idx / 150, k = idx - b * 150;
                u_s[b * 156 + k] = upi[idx];
            }
            for (int idx = tid; idx < Bn * 2; idx += NTHR)
                u_s[(idx >> 1) * 156 + 150 + (idx & 1)] = 0.f;
        }
        gsync(gen);

        // ---------- Phase B: g = u@WgU^T + cc@WgC^T ; rg = sig(g)*rbase ----------
        {
            float* u_s = sm + US_OFF;
            float* c_s = sm + BUF_OFF;          // 64 x 156
            for (int idx = tid; idx < Bn * 150; idx += NTHR) {
                int b = idx / 150, k = idx - b * 150;
                c_s[b * 156 + k] = d_cc[idx];
            }
            for (int idx = tid; idx < Bn * 2; idx += NTHR)
                c_s[(idx >> 1) * 156 + 150 + (idx & 1)] = 0.f;
            __syncthreads();
            const int j0 = (blk * 600) >> 7, j1 = ((blk + 1) * 600) >> 7;
            int b = tid & 63, jg = tid >> 6;
            for (int j = j0 + jg; j < j1; j += 4) {
                int jl = j - j0;
                float acc = 0.f;
                const float4* wu4 = (const float4*)(sm + WGU_OFF + jl * 152);
                const float4* wc4 = (const float4*)(sm + WGC_OFF + jl * 152);
                const float4* u4  = (const float4*)(u_s + b * 156);
                const float4* c4  = (const float4*)(c_s + b * 156);
#pragma unroll 19
                for (int q = 0; q < 38; q++) {
                    float4 a4 = u4[q], w4 = wu4[q];
                    float4 b4 = c4[q], x4 = wc4[q];
                    acc += a4.x * w4.x + a4.y * w4.y + a4.z * w4.z + a4.w * w4.w
                         + b4.x * x4.x + b4.y * x4.y + b4.z * x4.z + b4.w * x4.w;
                }
                float sg = fast_sig(acc);
                int km = j % 150;
                float rb = (j < 300) ? u_s[b * 156 + km] : c_s[b * 156 + km];
                d_rg[b * 600 + j] = sg * rb;
            }
        }
        gsync(gen);

        // ---------- Phase C: gi = rg@W_ih^T + b_ih ; GRU combine ----------
        {
            const int half = blk & 1;
            const int hb   = blk >> 1;
            const int b0   = half * 32;
            const int nt   = (hb < 22) ? 3 : 2;
            const int no   = 3 * nt;
            float* rg_s = sm + BUF_OFF;             // 32 rows, 151 f4 stride
            float* gi_s = sm + BUF_OFF + 19328;     // 9*32
            // prefetch GRU inputs (stable since Phase A) into registers
            const int tC = tid >> 5, blC = tid & 31;
            const bool act = (tid < 96) && (tC < nt);
            float hr = 0.f, hz = 0.f, hn = 0.f, vold = 0.f;
            int h2 = 0, b2 = 0;
            if (act) {
                h2 = hb + 64 * tC; b2 = b0 + blC;
                hr = d_gh[b2 * 450 + h2];
                hz = d_gh[b2 * 450 + 150 + h2];
                hn = d_gh[b2 * 450 + 300 + h2];
                vold = d_v[b2 * 150 + h2];
            }
            const float4* src = (const float4*)(d_rg + b0 * 600);
            float4* rg4 = (float4*)rg_s;
            for (int q = tid; q < 32 * 150; q += NTHR) {
                int bb = q / 150, kq = q - bb * 150;
                rg4[bb * 151 + kq] = src[bb * 150 + kq];
            }
            __syncthreads();
            const int bloc = tid & 31, og = tid >> 5;
            for (int o = og; o < no; o += 8) {
                int t = o / 3, g = o - 3 * t;
                int j = g * 150 + hb + 64 * t;
                float acc = b_ih[j];
                const float4* wr = (const float4*)(sm + WIH_OFF + o * 600);
                const float4* rr = rg4 + bloc * 151;
#pragma unroll 10
                for (int kq = 0; kq < 150; kq++) {
                    float4 a4 = rr[kq], w4 = wr[kq];
                    acc += a4.x * w4.x + a4.y * w4.y + a4.z * w4.z + a4.w * w4.w;
                }
                gi_s[o * 32 + bloc] = acc;
            }
            __syncthreads();
            if (act) {
                float ir  = gi_s[(tC * 3 + 0) * 32 + blC];
                float iz  = gi_s[(tC * 3 + 1) * 32 + blC];
                float in_ = gi_s[(tC * 3 + 2) * 32 + blC];
                float r_ = fast_sig(ir + hr);
                float z_ = fast_sig(iz + hz);
                float n_ = fast_tanh(in_ + r_ * hn);
                float hnew = (1.0f - z_) * n_ + z_ * vold;
                d_v[b2 * 150 + h2] = hnew;
                out[(i * Bn + b2) * 150 + h2] = hnew;
            }
        }
        gsync(gen);
    }
}

// ---------------- launch ----------------
extern "C" void kernel_launch(void* const* d_in, const int* in_sizes, int n_in,
                              void* d_out, int out_size)
{
    const float* Up   = (const float*)d_in[0];
    const float* Uq   = (const float*)d_in[1];
    const float* Wp   = (const float*)d_in[2];
    const float* Wq   = (const float*)d_in[3];
    const float* Wv   = (const float*)d_in[4];
    const float* Wg   = (const float*)d_in[5];
    const float* Vm   = (const float*)d_in[6];
    const float* v0   = (const float*)d_in[7];
    const float* W_ih = (const float*)d_in[8];
    const float* W_hh = (const float*)d_in[9];
    const float* b_ih = (const float*)d_in[10];
    const float* b_hh = (const float*)d_in[11];
    float* out = (float*)d_out;

    cudaFuncSetAttribute(pqm_kernel, cudaFuncAttributeMaxDynamicSharedMemorySize, SMEM_BYTES);
    pqm_kernel<<<NBLK, NTHR, SMEM_BYTES>>>(Up, Uq, Wp, Wq, Wv, Wg, Vm, v0,
                                           W_ih, W_hh, b_ih, b_hh, out);
}

// round 6
// speedup vs baseline: 1.1017x; 1.1017x over previous
#include <cuda_runtime.h>

// ---------------- problem constants ----------------
#define NBLK 128
#define NTHR 256
#define LPn  128
#define LQn  128
#define Bn   64
#define Hn   150

// ---------------- device scratch ----------------
__device__ float d_wup[LPn * Bn * Hn];   // [i][b][h]
__device__ float d_Wuq[Bn * LQn * Hn];   // [b][l][h]
__device__ float d_Uqt[Bn * LQn * Hn];   // [b][l][d]
__device__ float d_Wvt[150 * 152];       // transposed Wv: [k][h]
__device__ float d_WgU[600 * 150];
__device__ float d_WgC[600 * 150];
__device__ float d_gu[Bn * 600];         // u@WgU^T (precomputed per step)
__device__ float d_cc[Bn * 150];
__device__ float d_rg[Bn * 600];
__device__ float d_gh[Bn * 450];
__device__ float d_v[Bn * 150];
__device__ unsigned long long g_arrive;
__device__ unsigned long long g_release;

// ---------------- smem layout (floats) ----------------
// BUF (aliased):
//   P1: rowb 0..608, we 1024..23674
//   A(att): v_s 0..152, bse 152..304, a_s 304..432, ap 432..688
//   A(gh):  v_sp 0..9984 (64x156), u_sp 10000..19984 (64x156)
//   B:      c_s 0..9984 (64x156)
//   C:      rg 0..19328 (32x604), part 19400..21704 (8x288), gi 21704..21992
#define BUF_OFF   0
#define BUF_SZ    23936
#define WGC_OFF   (BUF_OFF + BUF_SZ)    // 5 x 152  (Phase B WgC slice)
#define WGUG_OFF  (WGC_OFF + 760)       // 10 x 152 (gh blocks: WgU gu-slice)
#define WIH_OFF   (WGUG_OFF + 1520)     // 9 x 600
#define WUQ_OFF   (WIH_OFF + 5400)      // att: 128 x 153 | gh: WHH 8 x 152
#define VB_OFF    (WUQ_OFF + 19584)     // 152
#define SMEM_FL   (VB_OFF + 152)        // 51352 floats
#define SMEM_BYTES (SMEM_FL * 4)        // 205408 B

// ---------------- helpers ----------------
__device__ __forceinline__ float warp_max_all(float v) {
#pragma unroll
    for (int o = 16; o > 0; o >>= 1) v = fmaxf(v, __shfl_xor_sync(0xffffffffu, v, o));
    return v;
}
__device__ __forceinline__ float warp_sum_all(float v) {
#pragma unroll
    for (int o = 16; o > 0; o >>= 1) v += __shfl_xor_sync(0xffffffffu, v, o);
    return v;
}
__device__ __forceinline__ float fast_sig(float x) {
    return 1.0f / (1.0f + __expf(-x));
}
__device__ __forceinline__ float fast_tanh(float x) {   // precise path (GRU)
    float cx = fminf(fmaxf(x, -15.0f), 15.0f);
    float e  = __expf(2.0f * cx);
    return __fdividef(e - 1.0f, e + 1.0f);
}
__device__ __forceinline__ float tanh_fastest(float x) { // attention path
    float y;
    asm("tanh.approx.f32 %0, %1;" : "=f"(y) : "f"(x));
    return y;
}

// Fence-free grid barrier: acq_rel arrival atomic + release store + acquire spin.
// NO __threadfence -> NO CCTL.IVALL -> L1D stays warm across the whole kernel.
// All cross-block data is accessed with ld.cg/st.cg (L1-bypass), so L1 can
// never hold stale copies of it; the release/acquire pair gives ordering.
__device__ __forceinline__ void gsync(unsigned long long& gen) {
    __syncthreads();
    if (threadIdx.x == 0) {
        unsigned long long target = ++gen;
        unsigned long long one = 1ULL, t;
        asm volatile("atom.acq_rel.gpu.add.u64 %0, [%1], %2;"
                     : "=l"(t) : "l"(&g_arrive), "l"(one) : "memory");
        if (t == target * (unsigned long long)NBLK - 1ULL) {
            asm volatile("st.release.gpu.u64 [%0], %1;"
                         :: "l"(&g_release), "l"(target) : "memory");
        } else {
            unsigned long long r;
            do {
                asm volatile("ld.acquire.gpu.u64 %0, [%1];"
                             : "=l"(r) : "l"(&g_release) : "memory");
            } while (r < target);
        }
    }
    __syncthreads();
}

// Phase C inner MMA: warp handles f4-range [q0,q1) for NO output rows.
template<int NO>
__device__ __forceinline__ void phaseC_mma(const float4* __restrict__ rr,
                                           const float4* __restrict__ wih,
                                           int q0, int q1,
                                           float* __restrict__ part,
                                           int w, int ln) {
    float acc[NO];
#pragma unroll
    for (int o = 0; o < NO; o++) acc[o] = 0.f;
    for (int q = q0; q < q1; q++) {
        float4 a4 = rr[q];
#pragma unroll
        for (int o = 0; o < NO; o++) {
            float4 w4 = wih[o * 150 + q];
            acc[o] += a4.x * w4.x + a4.y * w4.y + a4.z * w4.z + a4.w * w4.w;
        }
    }
#pragma unroll
    for (int o = 0; o < NO; o++) part[w * 288 + o * 32 + ln] = acc[o];
}

// ---------------- the persistent kernel ----------------
__global__ void __launch_bounds__(NTHR, 1) pqm_kernel(
    const float* __restrict__ Up, const float* __restrict__ Uq,
    const float* __restrict__ Wp, const float* __restrict__ Wq,
    const float* __restrict__ Wv, const float* __restrict__ Wg,
    const float* __restrict__ Vmat, const float* __restrict__ v0,
    const float* __restrict__ W_ih, const float* __restrict__ W_hh,
    const float* __restrict__ b_ih, const float* __restrict__ b_hh,
    float* __restrict__ out)
{
    extern __shared__ float sm[];
    const int tid = threadIdx.x;
    const int blk = blockIdx.x;

    unsigned long long gen = 0;
    if (tid == 0) gen = *((volatile unsigned long long*)&g_release);

    // ======== P0: fold Wg; transpose Wv; copy v0 ========
    for (int idx = blk * NTHR + tid; idx < 600 * 150; idx += NBLK * NTHR) {
        int j = idx / 150, k = idx - j * 150;
        d_WgU[idx] = Wg[j * 600 + k]       + Wg[j * 600 + 150 + k];
        d_WgC[idx] = Wg[j * 600 + 300 + k] + Wg[j * 600 + 450 + k];
    }
    for (int idx = blk * NTHR + tid; idx < 150 * 150; idx += NBLK * NTHR) {
        int h = idx / 150, k = idx - h * 150;
        d_Wvt[k * 152 + h] = Wv[idx];
    }
    for (int idx = blk * NTHR + tid; idx < Bn * 150; idx += NBLK * NTHR)
        d_v[idx] = v0[idx];
    gsync(gen);

    // ======== P1: hoist wup, Wuq (relayout), Uqt transpose ========
    {
        float* rowb = sm + BUF_OFF;           // 4*152
        float* we   = sm + BUF_OFF + 1024;    // 150*151
        const int m = blk;
        for (int idx = tid; idx < 150 * 150; idx += NTHR) {
            int h = idx / 150, d = idx - h * 150;
            we[h * 151 + d] = Wp[h * 300 + d] + Wp[h * 300 + 150 + d];
        }
        __syncthreads();
        for (int b0 = 0; b0 < Bn; b0 += 4) {
            for (int idx = tid; idx < 600; idx += NTHR) {
                int j = idx / 150, d = idx - j * 150;
                rowb[j * 152 + d] = Up[(m * Bn + b0 + j) * 150 + d];
            }
            __syncthreads();
            if (tid < 150) {
                float a0 = 0.f, a1 = 0.f, a2 = 0.f, a3 = 0.f;
                const float* wr = we + tid * 151;
#pragma unroll 6
                for (int k = 0; k < 150; k++) {
                    float w = wr[k];
                    a0 += w * rowb[k];       a1 += w * rowb[152 + k];
                    a2 += w * rowb[304 + k]; a3 += w * rowb[456 + k];
                }
                d_wup[(m * Bn + b0 + 0) * 150 + tid] = a0;
                d_wup[(m * Bn + b0 + 1) * 150 + tid] = a1;
                d_wup[(m * Bn + b0 + 2) * 150 + tid] = a2;
                d_wup[(m * Bn + b0 + 3) * 150 + tid] = a3;
            }
            __syncthreads();
        }
        for (int idx = tid; idx < 150 * 150; idx += NTHR) {
            int h = idx / 150, d = idx - h * 150;
            we[h * 151 + d] = Wq[h * 300 + d] + Wq[h * 300 + 150 + d];
        }
        __syncthreads();
        for (int b0 = 0; b0 < Bn; b0 += 4) {
            for (int idx = tid; idx < 600; idx += NTHR) {
                int j = idx / 150, d = idx - j * 150;
                float vv = Uq[(m * Bn + b0 + j) * 150 + d];
                rowb[j * 152 + d] = vv;
                d_Uqt[((b0 + j) * LQn + m) * 150 + d] = vv;
            }
            __syncthreads();
            if (tid < 150) {
                float a0 = 0.f, a1 = 0.f, a2 = 0.f, a3 = 0.f;
                const float* wr = we + tid * 151;
#pragma unroll 6
                for (int k = 0; k < 150; k++) {
                    float w = wr[k];
                    a0 += w * rowb[k];       a1 += w * rowb[152 + k];
                    a2 += w * rowb[304 + k]; a3 += w * rowb[456 + k];
                }
                d_Wuq[((b0 + 0) * LQn + m) * 150 + tid] = a0;
                d_Wuq[((b0 + 1) * LQn + m) * 150 + tid] = a1;
                d_Wuq[((b0 + 2) * LQn + m) * 150 + tid] = a2;
                d_Wuq[((b0 + 3) * LQn + m) * 150 + tid] = a3;
            }
            __syncthreads();
        }
    }
    gsync(gen);

    // ======== persistent smem weight slices ========
    {
        // Phase B WgC slice (rows j0b..j1b, padded to 152)
        int j0b = (blk * 600) >> 7, nrb = (((blk + 1) * 600) >> 7) - j0b;
        for (int idx = tid; idx < nrb * 152; idx += NTHR) {
            int r = idx / 152, k = idx - r * 152;
            sm[WGC_OFF + idx] = (k < 150) ? __ldcg(&d_WgC[(j0b + r) * 150 + k]) : 0.f;
        }
        // Phase C W_ih slice (row order o = t*3+g), rows of 600
        int hb = blk >> 1;
        int nt = (hb < 22) ? 3 : 2;
        for (int idx = tid; idx < nt * 3 * 600; idx += NTHR) {
            int o = idx / 600, k = idx - o * 600;
            int t = o / 3, g = o - 3 * t;
            int j = g * 150 + hb + 64 * t;
            sm[WIH_OFF + idx] = W_ih[j * 600 + k];
        }
        if (blk >= Bn) {
            int bk = blk - Bn;
            // W_hh slice (gh), padded to 152
            int j0g = (bk * 450) >> 6, nrg = (((bk + 1) * 450) >> 6) - j0g;
            for (int idx = tid; idx < nrg * 152; idx += NTHR) {
                int r = idx / 152, k = idx - r * 152;
                sm[WUQ_OFF + idx] = (k < 150) ? W_hh[(j0g + r) * 150 + k] : 0.f;
            }
            // WgU slice for gu precompute, padded to 152
            int j0u = (bk * 600) >> 6, nru = (((bk + 1) * 600) >> 6) - j0u;
            for (int idx = tid; idx < nru * 152; idx += NTHR) {
                int r = idx / 152, k = idx - r * 152;
                sm[WGUG_OFF + idx] = (k < 150) ? __ldcg(&d_WgU[(j0u + r) * 150 + k]) : 0.f;
            }
        } else {
            // Wuq slice (stride 153, conflict-free scalar) + V row
            const float* src = d_Wuq + blk * (LQn * 150);
            for (int idx = tid; idx < LQn * 150; idx += NTHR) {
                int l = idx / 150, k = idx - l * 150;
                sm[WUQ_OFF + l * 153 + k] = __ldcg(&src[idx]);
            }
            if (tid < 150) sm[VB_OFF + tid] = Vmat[blk * 150 + tid];
        }
    }
    gsync(gen);

    const int w  = tid >> 5, ln = tid & 31;

    // ======== main scan ========
    for (int i = 0; i < LPn; i++) {
        // ---------- Phase A ----------
        if (blk < Bn) {
            const int b = blk;
            float* v_s = sm + BUF_OFF;
            float* bse = sm + BUF_OFF + 152;
            float* a_s = sm + BUF_OFF + 304;
            float* ap  = sm + BUF_OFF + 432;
            if (tid < 150) {
                v_s[tid] = __ldcg(&d_v[b * 150 + tid]);
                bse[tid] = __ldcg(&d_wup[(i * Bn + b) * 150 + tid]);
            }
            __syncthreads();
            // wv: thread-per-h over transposed Wvt (coalesced, no reductions)
            if (tid < 150) {
                float acc = 0.f;
                const float* col = d_Wvt + tid;
#pragma unroll 10
                for (int k = 0; k < 150; k++)
                    acc += v_s[k] * __ldcg(&col[k * 152]);
                bse[tid] += acc;
            }
            __syncthreads();
            // s[l]: thread-per-(l, k-half), smem Wuq stride 153
            {
                int l = tid & 127, g = tid >> 7;
                const float* wq = sm + WUQ_OFF + l * 153 + g * 75;
                const float* bp = bse + g * 75;
                const float* vp = sm + VB_OFF + g * 75;
                float acc = 0.f;
#pragma unroll 15
                for (int k = 0; k < 75; k++)
                    acc += tanh_fastest(bp[k] + wq[k]) * vp[k];
                ap[g * 128 + l] = acc;
            }
            __syncthreads();
            // softmax (warp 0), combining the two k-halves
            if (w == 0) {
                float a0 = ap[ln]      + ap[128 + ln];
                float a1 = ap[ln + 32] + ap[160 + ln];
                float a2 = ap[ln + 64] + ap[192 + ln];
                float a3 = ap[ln + 96] + ap[224 + ln];
                float m = fmaxf(fmaxf(a0, a1), fmaxf(a2, a3));
                m = warp_max_all(m);
                float e0 = __expf(a0 - m), e1 = __expf(a1 - m);
                float e2 = __expf(a2 - m), e3 = __expf(a3 - m);
                float ssum = warp_sum_all(e0 + e1 + e2 + e3);
                float inv = __fdividef(1.0f, ssum);
                a_s[ln] = e0 * inv; a_s[ln + 32] = e1 * inv;
                a_s[ln + 64] = e2 * inv; a_s[ln + 96] = e3 * inv;
            }
            __syncthreads();
            // cc[d]: thread-per-d, coalesced Uqt rows
            if (tid < 150) {
                float acc = 0.f;
                const float* uq = d_Uqt + b * (LQn * 150) + tid;
#pragma unroll 8
                for (int l = 0; l < LQn; l++)
                    acc += a_s[l] * __ldcg(&uq[l * 150]);
                __stcg(&d_cc[b * 150 + tid], acc);
            }
        } else {
            // gh = v@W_hh^T + b_hh  AND  gu = u@WgU^T  (cc-independent)
            const int bk = blk - Bn;
            const int j0g = (bk * 450) >> 6, j1g = ((bk + 1) * 450) >> 6;
            const int j0u = (bk * 600) >> 6, j1u = ((bk + 1) * 600) >> 6;
            float* v_sp = sm + BUF_OFF;           // 64x156 (+pad zeros)
            float* u_sp = sm + BUF_OFF + 10000;   // 64x156 (+pad zeros)
            const float* upi = Up + i * Bn * 150;
            for (int idx = tid; idx < Bn * 156; idx += NTHR) {
                int b = idx / 156, k = idx - b * 156;
                v_sp[idx] = (k < 150) ? __ldcg(&d_v[b * 150 + k]) : 0.f;
                u_sp[idx] = (k < 150) ? upi[b * 150 + k] : 0.f;
            }
            __syncthreads();
            int b = tid & 63, jg = tid >> 6;
            const float4* vr4 = (const float4*)(v_sp + b * 156);
            const float4* ur4 = (const float4*)(u_sp + b * 156);
            for (int j = j0g + jg; j < j1g; j += 4) {
                int jl = j - j0g;
                float acc = b_hh[j];
                const float4* wr4 = (const float4*)(sm + WUQ_OFF + jl * 152);
#pragma unroll 19
                for (int q = 0; q < 38; q++) {
                    float4 a4 = vr4[q], w4 = wr4[q];
                    acc += a4.x * w4.x + a4.y * w4.y + a4.z * w4.z + a4.w * w4.w;
                }
                __stcg(&d_gh[b * 450 + j], acc);
            }
            for (int j = j0u + jg; j < j1u; j += 4) {
                int jl = j - j0u;
                float acc = 0.f;
                const float4* wr4 = (const float4*)(sm + WGUG_OFF + jl * 152);
#pragma unroll 19
                for (int q = 0; q < 38; q++) {
                    float4 a4 = ur4[q], w4 = wr4[q];
                    acc += a4.x * w4.x + a4.y * w4.y + a4.z * w4.z + a4.w * w4.w;
                }
                __stcg(&d_gu[b * 600 + j], acc);
            }
        }
        gsync(gen);

        // ---------- Phase B: g = gu + cc@WgC^T ; rg = sig(g)*rbase ----------
        {
            float* c_s = sm + BUF_OFF;   // 64x156 (+pad zeros)
            for (int idx = tid; idx < Bn * 156; idx += NTHR) {
                int b = idx / 156, k = idx - b * 156;
                c_s[idx] = (k < 150) ? __ldcg(&d_cc[b * 150 + k]) : 0.f;
            }
            __syncthreads();
            const int j0 = (blk * 600) >> 7, j1 = ((blk + 1) * 600) >> 7;
            int b = tid & 63, jg = tid >> 6;
            const float4* cr4 = (const float4*)(c_s + b * 156);
            for (int j = j0 + jg; j < j1; j += 4) {
                int jl = j - j0;
                float acc = __ldcg(&d_gu[b * 600 + j]);
                const float4* wc4 = (const float4*)(sm + WGC_OFF + jl * 152);
#pragma unroll 19
                for (int q = 0; q < 38; q++) {
                    float4 a4 = cr4[q], w4 = wc4[q];
                    acc += a4.x * w4.x + a4.y * w4.y + a4.z * w4.z + a4.w * w4.w;
                }
                float sg = fast_sig(acc);
                int km = j % 150;
                float rb = (j < 300) ? __ldg(&Up[i * Bn * 150 + b * 150 + km])
                                     : c_s[b * 156 + km];
                __stcg(&d_rg[b * 600 + j], sg * rb);
            }
        }
        gsync(gen);

        // ---------- Phase C: gi = rg@W_ih^T + b_ih ; GRU combine ----------
        {
            const int half = blk & 1;
            const int hb   = blk >> 1;
            const int b0   = half * 32;
            const int nt   = (hb < 22) ? 3 : 2;
            const int no   = 3 * nt;
            float* rg_s = sm + BUF_OFF;              // 32 rows, 151-f4 stride
            float* part = sm + BUF_OFF + 19400;      // [w][o][lane]
            float* gi_s = sm + BUF_OFF + 21704;      // no*32
            // prefetch GRU inputs (stable since Phase A) into registers
            const int tC = tid >> 5, blC = tid & 31;
            const bool act = (tid < 96) && (tC < nt);
            float hr = 0.f, hz = 0.f, hn = 0.f, vold = 0.f;
            int h2 = 0, b2 = 0;
            if (act) {
                h2 = hb + 64 * tC; b2 = b0 + blC;
                hr = __ldcg(&d_gh[b2 * 450 + h2]);
                hz = __ldcg(&d_gh[b2 * 450 + 150 + h2]);
                hn = __ldcg(&d_gh[b2 * 450 + 300 + h2]);
                vold = __ldcg(&d_v[b2 * 150 + h2]);
            }
            const float4* src = (const float4*)(d_rg + b0 * 600);
            float4* rg4 = (float4*)rg_s;
            for (int q = tid; q < 32 * 150; q += NTHR) {
                int bb = q / 150, kq = q - bb * 150;
                float4 vsrc = __ldcg(&src[bb * 150 + kq]);
                rg4[bb * 151 + kq] = vsrc;
            }
            __syncthreads();
            // k-split MMA: warp w owns f4-range [19w, min(19w+19,150))
            {
                int q0 = 19 * w, q1 = (q0 + 19 < 150) ? q0 + 19 : 150;
                const float4* rr  = rg4 + ln * 151;
                const float4* wih = (const float4*)(sm + WIH_OFF);
                if (nt == 3) phaseC_mma<9>(rr, wih, q0, q1, part, w, ln);
                else         phaseC_mma<6>(rr, wih, q0, q1, part, w, ln);
            }
            __syncthreads();
            // reduce partials + bias
            for (int idx = tid; idx < no * 32; idx += NTHR) {
                int o = idx >> 5;
                float s = 0.f;
#pragma unroll
                for (int ww = 0; ww < 8; ww++) s += part[ww * 288 + idx];
                int t = o / 3, g = o - 3 * t;
                gi_s[idx] = s + __ldg(&b_ih[g * 150 + hb + 64 * t]);
            }
            __syncthreads();
            if (act) {
                float ir  = gi_s[(tC * 3 + 0) * 32 + blC];
                float iz  = gi_s[(tC * 3 + 1) * 32 + blC];
                float in_ = gi_s[(tC * 3 + 2) * 32 + blC];
                float r_ = fast_sig(ir + hr);
                float z_ = fast_sig(iz + hz);
                float n_ = fast_tanh(in_ + r_ * hn);
                float hnew = (1.0f - z_) * n_ + z_ * vold;
                __stcg(&d_v[b2 * 150 + h2], hnew);
                out[(i * Bn + b2) * 150 + h2] = hnew;
            }
        }
        gsync(gen);
    }
}

// ---------------- launch ----------------
extern "C" void kernel_launch(void* const* d_in, const int* in_sizes, int n_in,
                              void* d_out, int out_size)
{
    const float* Up   = (const float*)d_in[0];
    const float* Uq   = (const float*)d_in[1];
    const float* Wp   = (const float*)d_in[2];
    const float* Wq   = (const float*)d_in[3];
    const float* Wv   = (const float*)d_in[4];
    const float* Wg   = (const float*)d_in[5];
    const float* Vm   = (const float*)d_in[6];
    const float* v0   = (const float*)d_in[7];
    const float* W_ih = (const float*)d_in[8];
    const float* W_hh = (const float*)d_in[9];
    const float* b_ih = (const float*)d_in[10];
    const float* b_hh = (const float*)d_in[11];
    float* out = (float*)d_out;

    cudaFuncSetAttribute(pqm_kernel, cudaFuncAttributeMaxDynamicSharedMemorySize, SMEM_BYTES);
    pqm_kernel<<<NBLK, NTHR, SMEM_BYTES>>>(Up, Uq, Wp, Wq, Wv, Wg, Vm, v0,
                                           W_ih, W_hh, b_ih, b_hh, out);
}

// round 7
// speedup vs baseline: 1.1077x; 1.0054x over previous
#include <cuda_runtime.h>

// ---------------- problem constants ----------------
#define NBLK 128
#define NTHR 512
#define LPn  128
#define LQn  128
#define Bn   64
#define Hn   150

// ---------------- device scratch ----------------
__device__ float d_wup[LPn * Bn * Hn];   // [i][b][h]   (write-once)
__device__ float d_Wuq[Bn * LQn * Hn];   // [b][l][h]   (write-once)
__device__ float d_Uqt[Bn * LQn * Hn];   // [b][l][d]   (write-once)
__device__ float d_Wvt[150 * 152];       // [k][h]      (write-once)
__device__ float d_WgU[600 * 150];       // (write-once)
__device__ float d_WgC[600 * 150];       // (write-once)
__device__ float d_gu[Bn * 600];         // per-step
__device__ float d_cc[Bn * 150];         // per-step
__device__ float d_rg[Bn * 600];         // per-step
__device__ float d_gh[Bn * 450];         // per-step
__device__ float d_v[Bn * 150];          // per-step
__device__ unsigned g_flags[NBLK];       // monotonic, never reset
__device__ unsigned g_rel2;              // monotonic, never reset

// ---------------- smem layout (floats) ----------------
// BUF aliased per phase:
//  P1:    rowb 0..608, we 1024..23674
//  A att: v_s 0..152, bse 152..304, a_s 304..432, ap 432..944,
//         wvp 944..1248, ccp 1248..1552
//  A gh:  v_sp 0..9984 (64x156), u_sp 10000..19984 (64x156)
//  B:     c_s 0..9984 (64x156)
//  C:     rg 0..19328 (32x604), part 19400..24008 (16x288), gi 24008..24296
#define BUF_OFF   0
#define BUF_SZ    24320
#define WGC_OFF   (BUF_OFF + BUF_SZ)    // 5 x 152   (Phase B WgC slice)
#define WGUG_OFF  (WGC_OFF + 760)       // 10 x 152  (gh blocks: WgU slice)
#define WIH_OFF   (WGUG_OFF + 1520)     // 9 x 600   (Phase C slice)
#define WUQ_OFF   (WIH_OFF + 5400)      // att: 128x153 | gh: WHH 8x152
#define VB_OFF    (WUQ_OFF + 19584)     // 152
#define SMEM_FL   (VB_OFF + 152)        // 51736 floats
#define SMEM_BYTES (SMEM_FL * 4)        // 206944 B

// ---------------- helpers ----------------
__device__ __forceinline__ float warp_max_all(float v) {
#pragma unroll
    for (int o = 16; o > 0; o >>= 1) v = fmaxf(v, __shfl_xor_sync(0xffffffffu, v, o));
    return v;
}
__device__ __forceinline__ float warp_sum_all(float v) {
#pragma unroll
    for (int o = 16; o > 0; o >>= 1) v += __shfl_xor_sync(0xffffffffu, v, o);
    return v;
}
__device__ __forceinline__ float fast_sig(float x) {
    return 1.0f / (1.0f + __expf(-x));
}
__device__ __forceinline__ float fast_tanh(float x) {   // precise path (GRU)
    float cx = fminf(fmaxf(x, -15.0f), 15.0f);
    float e  = __expf(2.0f * cx);
    return __fdividef(e - 1.0f, e + 1.0f);
}
__device__ __forceinline__ float tanh_fastest(float x) { // attention path
    float y;
    asm("tanh.approx.f32 %0, %1;" : "=f"(y) : "f"(x));
    return y;
}

// Flag-array grid barrier: NO atomics.
//  - every non-zero block: one st.release to its OWN flag slot, then spins
//    (acquire) on the release word.
//  - block 0, warp 0: polls all 128 flags cooperatively (4 acquire loads per
//    lane + __all_sync), then one st.release to the release word.
// Release->acquire chains are transitive (PTX mem model), so all prior writes
// of every block are visible to every block after the barrier. Monotonic
// counters -> safe across graph replays. No fences -> L1D never invalidated;
// all cross-block mutable data uses ld.cg/st.cg (L1-bypass) instead.
__device__ __forceinline__ void gsync(unsigned& gen) {
    __syncthreads();
    const unsigned target = gen + 1u;
    if (blockIdx.x == 0) {
        if (threadIdx.x < 32) {
            const int ln = threadIdx.x;
            if (ln == 0) *((volatile unsigned*)&g_flags[0]) = target;
            bool ok;
            do {
                unsigned f0, f1, f2, f3;
                asm volatile("ld.acquire.gpu.u32 %0, [%1];" : "=r"(f0) : "l"(&g_flags[ln]));
                asm volatile("ld.acquire.gpu.u32 %0, [%1];" : "=r"(f1) : "l"(&g_flags[ln + 32]));
                asm volatile("ld.acquire.gpu.u32 %0, [%1];" : "=r"(f2) : "l"(&g_flags[ln + 64]));
                asm volatile("ld.acquire.gpu.u32 %0, [%1];" : "=r"(f3) : "l"(&g_flags[ln + 96]));
                ok = (f0 >= target) & (f1 >= target) & (f2 >= target) & (f3 >= target);
            } while (!__all_sync(0xffffffffu, ok));
            if (ln == 0)
                asm volatile("st.release.gpu.u32 [%0], %1;" :: "l"(&g_rel2), "r"(target) : "memory");
        }
    } else {
        if (threadIdx.x == 0) {
            asm volatile("st.release.gpu.u32 [%0], %1;"
                         :: "l"(&g_flags[blockIdx.x]), "r"(target) : "memory");
            unsigned r;
            do {
                asm volatile("ld.acquire.gpu.u32 %0, [%1];" : "=r"(r) : "l"(&g_rel2));
            } while (r < target);
        }
    }
    gen = target;
    __syncthreads();
}

// Phase C inner MMA: warp handles f4-range [q0,q1) for NO output rows.
template<int NO>
__device__ __forceinline__ void phaseC_mma(const float4* __restrict__ rr,
                                           const float4* __restrict__ wih,
                                           int q0, int q1,
                                           float* __restrict__ part,
                                           int w, int ln) {
    float acc[NO];
#pragma unroll
    for (int o = 0; o < NO; o++) acc[o] = 0.f;
    for (int q = q0; q < q1; q++) {
        float4 a4 = rr[q];
#pragma unroll
        for (int o = 0; o < NO; o++) {
            float4 w4 = wih[o * 150 + q];
            acc[o] += a4.x * w4.x + a4.y * w4.y + a4.z * w4.z + a4.w * w4.w;
        }
    }
#pragma unroll
    for (int o = 0; o < NO; o++) part[w * 288 + o * 32 + ln] = acc[o];
}

// ---------------- the persistent kernel ----------------
__global__ void __launch_bounds__(NTHR, 1) pqm_kernel(
    const float* __restrict__ Up, const float* __restrict__ Uq,
    const float* __restrict__ Wp, const float* __restrict__ Wq,
    const float* __restrict__ Wv, const float* __restrict__ Wg,
    const float* __restrict__ Vmat, const float* __restrict__ v0,
    const float* __restrict__ W_ih, const float* __restrict__ W_hh,
    const float* __restrict__ b_ih, const float* __restrict__ b_hh,
    float* __restrict__ out)
{
    extern __shared__ float sm[];
    const int tid = threadIdx.x;
    const int blk = blockIdx.x;

    unsigned gen = *((volatile unsigned*)&g_rel2);

    // ======== P0: fold Wg; transpose Wv; copy v0 ========
    for (int idx = blk * NTHR + tid; idx < 600 * 150; idx += NBLK * NTHR) {
        int j = idx / 150, k = idx - j * 150;
        d_WgU[idx] = Wg[j * 600 + k]       + Wg[j * 600 + 150 + k];
        d_WgC[idx] = Wg[j * 600 + 300 + k] + Wg[j * 600 + 450 + k];
    }
    for (int idx = blk * NTHR + tid; idx < 150 * 150; idx += NBLK * NTHR) {
        int h = idx / 150, k = idx - h * 150;
        d_Wvt[k * 152 + h] = Wv[idx];
    }
    for (int idx = blk * NTHR + tid; idx < Bn * 150; idx += NBLK * NTHR)
        __stcg(&d_v[idx], v0[idx]);
    gsync(gen);

    // ======== P1: hoist wup, Wuq (relayout), Uqt transpose ========
    {
        float* rowb = sm + BUF_OFF;           // 4*152
        float* we   = sm + BUF_OFF + 1024;    // 150*151
        const int m = blk;
        for (int idx = tid; idx < 150 * 150; idx += NTHR) {
            int h = idx / 150, d = idx - h * 150;
            we[h * 151 + d] = Wp[h * 300 + d] + Wp[h * 300 + 150 + d];
        }
        __syncthreads();
        for (int b0 = 0; b0 < Bn; b0 += 4) {
            for (int idx = tid; idx < 600; idx += NTHR) {
                int j = idx / 150, d = idx - j * 150;
                rowb[j * 152 + d] = Up[(m * Bn + b0 + j) * 150 + d];
            }
            __syncthreads();
            if (tid < 150) {
                float a0 = 0.f, a1 = 0.f, a2 = 0.f, a3 = 0.f;
                const float* wr = we + tid * 151;
#pragma unroll 6
                for (int k = 0; k < 150; k++) {
                    float w = wr[k];
                    a0 += w * rowb[k];       a1 += w * rowb[152 + k];
                    a2 += w * rowb[304 + k]; a3 += w * rowb[456 + k];
                }
                d_wup[(m * Bn + b0 + 0) * 150 + tid] = a0;
                d_wup[(m * Bn + b0 + 1) * 150 + tid] = a1;
                d_wup[(m * Bn + b0 + 2) * 150 + tid] = a2;
                d_wup[(m * Bn + b0 + 3) * 150 + tid] = a3;
            }
            __syncthreads();
        }
        for (int idx = tid; idx < 150 * 150; idx += NTHR) {
            int h = idx / 150, d = idx - h * 150;
            we[h * 151 + d] = Wq[h * 300 + d] + Wq[h * 300 + 150 + d];
        }
        __syncthreads();
        for (int b0 = 0; b0 < Bn; b0 += 4) {
            for (int idx = tid; idx < 600; idx += NTHR) {
                int j = idx / 150, d = idx - j * 150;
                float vv = Uq[(m * Bn + b0 + j) * 150 + d];
                rowb[j * 152 + d] = vv;
                d_Uqt[((b0 + j) * LQn + m) * 150 + d] = vv;
            }
            __syncthreads();
            if (tid < 150) {
                float a0 = 0.f, a1 = 0.f, a2 = 0.f, a3 = 0.f;
                const float* wr = we + tid * 151;
#pragma unroll 6
                for (int k = 0; k < 150; k++) {
                    float w = wr[k];
                    a0 += w * rowb[k];       a1 += w * rowb[152 + k];
                    a2 += w * rowb[304 + k]; a3 += w * rowb[456 + k];
                }
                d_Wuq[((b0 + 0) * LQn + m) * 150 + tid] = a0;
                d_Wuq[((b0 + 1) * LQn + m) * 150 + tid] = a1;
                d_Wuq[((b0 + 2) * LQn + m) * 150 + tid] = a2;
                d_Wuq[((b0 + 3) * LQn + m) * 150 + tid] = a3;
            }
            __syncthreads();
        }
    }
    gsync(gen);

    // ======== persistent smem weight slices ========
    {
        int j0b = (blk * 600) >> 7, nrb = (((blk + 1) * 600) >> 7) - j0b;
        for (int idx = tid; idx < nrb * 152; idx += NTHR) {
            int r = idx / 152, k = idx - r * 152;
            sm[WGC_OFF + idx] = (k < 150) ? d_WgC[(j0b + r) * 150 + k] : 0.f;
        }
        int hb = blk >> 1;
        int nt = (hb < 22) ? 3 : 2;
        for (int idx = tid; idx < nt * 3 * 600; idx += NTHR) {
            int o = idx / 600, k = idx - o * 600;
            int t = o / 3, g = o - 3 * t;
            int j = g * 150 + hb + 64 * t;
            sm[WIH_OFF + idx] = W_ih[j * 600 + k];
        }
        if (blk >= Bn) {
            int bk = blk - Bn;
            int j0g = (bk * 450) >> 6, nrg = (((bk + 1) * 450) >> 6) - j0g;
            for (int idx = tid; idx < nrg * 152; idx += NTHR) {
                int r = idx / 152, k = idx - r * 152;
                sm[WUQ_OFF + idx] = (k < 150) ? W_hh[(j0g + r) * 150 + k] : 0.f;
            }
            int j0u = (bk * 600) >> 6, nru = (((bk + 1) * 600) >> 6) - j0u;
            for (int idx = tid; idx < nru * 152; idx += NTHR) {
                int r = idx / 152, k = idx - r * 152;
                sm[WGUG_OFF + idx] = (k < 150) ? d_WgU[(j0u + r) * 150 + k] : 0.f;
            }
        } else {
            const float* src = d_Wuq + blk * (LQn * 150);
            for (int idx = tid; idx < LQn * 150; idx += NTHR) {
                int l = idx / 150, k = idx - l * 150;
                sm[WUQ_OFF + l * 153 + k] = src[idx];
            }
            if (tid < 150) sm[VB_OFF + tid] = Vmat[blk * 150 + tid];
        }
    }
    gsync(gen);

    const int w  = tid >> 5, ln = tid & 31;

    // ======== main scan ========
    for (int i = 0; i < LPn; i++) {
        // ---------- Phase A ----------
        if (blk < Bn) {
            const int b = blk;
            float* v_s = sm + BUF_OFF;
            float* bse = sm + BUF_OFF + 152;
            float* a_s = sm + BUF_OFF + 304;
            float* ap  = sm + BUF_OFF + 432;    // 512
            float* wvp = sm + BUF_OFF + 944;    // 2 x 152
            float* ccp = sm + BUF_OFF + 1248;   // 2 x 152
            if (tid < 150) {
                v_s[tid] = __ldcg(&d_v[b * 150 + tid]);
                bse[tid] = d_wup[(i * Bn + b) * 150 + tid];
            }
            __syncthreads();
            // wv: (h, k-half) split over 300 threads, Wvt coalesced
            if (tid < 300) {
                int g = tid / 150, h = tid - g * 150;
                int k0 = 75 * g;
                const float* col = d_Wvt + h;
                float acc = 0.f;
#pragma unroll 15
                for (int k = 0; k < 75; k++)
                    acc += v_s[k0 + k] * col[(k0 + k) * 152];
                wvp[g * 152 + h] = acc;
            }
            __syncthreads();
            if (tid < 150) bse[tid] += wvp[tid] + wvp[152 + tid];
            __syncthreads();
            // s[l]: (l, k-quarter) split over all 512 threads
            {
                int l = tid & 127, g = tid >> 7;
                int k0 = (g * 150) >> 2, k1 = ((g + 1) * 150) >> 2;
                const float* wq = sm + WUQ_OFF + l * 153;
                const float* vp = sm + VB_OFF;
                float acc = 0.f;
#pragma unroll 10
                for (int k = k0; k < k1; k++)
                    acc += tanh_fastest(bse[k] + wq[k]) * vp[k];
                ap[g * 128 + l] = acc;
            }
            __syncthreads();
            // softmax (warp 0), combining the four k-quarters
            if (w == 0) {
                float a0 = ap[ln]      + ap[128 + ln]      + ap[256 + ln]      + ap[384 + ln];
                float a1 = ap[ln + 32] + ap[128 + ln + 32] + ap[256 + ln + 32] + ap[384 + ln + 32];
                float a2 = ap[ln + 64] + ap[128 + ln + 64] + ap[256 + ln + 64] + ap[384 + ln + 64];
                float a3 = ap[ln + 96] + ap[128 + ln + 96] + ap[256 + ln + 96] + ap[384 + ln + 96];
                float m = fmaxf(fmaxf(a0, a1), fmaxf(a2, a3));
                m = warp_max_all(m);
                float e0 = __expf(a0 - m), e1 = __expf(a1 - m);
                float e2 = __expf(a2 - m), e3 = __expf(a3 - m);
                float ssum = warp_sum_all(e0 + e1 + e2 + e3);
                float inv = __fdividef(1.0f, ssum);
                a_s[ln] = e0 * inv; a_s[ln + 32] = e1 * inv;
                a_s[ln + 64] = e2 * inv; a_s[ln + 96] = e3 * inv;
            }
            __syncthreads();
            // cc: (d, l-half) split over 300 threads, coalesced Uqt rows
            if (tid < 300) {
                int g = tid / 150, d = tid - g * 150;
                const float* uq = d_Uqt + (b * LQn + g * 64) * 150 + d;
                const float* av = a_s + g * 64;
                float acc = 0.f;
#pragma unroll 16
                for (int t = 0; t < 64; t++)
                    acc += av[t] * uq[t * 150];
                ccp[g * 152 + d] = acc;
            }
            __syncthreads();
            if (tid < 150)
                __stcg(&d_cc[b * 150 + tid], ccp[tid] + ccp[152 + tid]);
        } else {
            // gh = v@W_hh^T + b_hh  AND  gu = u@WgU^T  (cc-independent)
            const int bk = blk - Bn;
            const int j0g = (bk * 450) >> 6, j1g = ((bk + 1) * 450) >> 6;
            const int j0u = (bk * 600) >> 6, j1u = ((bk + 1) * 600) >> 6;
            float* v_sp = sm + BUF_OFF;           // 64x156 (+pad zeros)
            float* u_sp = sm + BUF_OFF + 10000;   // 64x156 (+pad zeros)
            const float* upi = Up + i * Bn * 150;
            for (int idx = tid; idx < Bn * 156; idx += NTHR) {
                int b = idx / 156, k = idx - b * 156;
                v_sp[idx] = (k < 150) ? __ldcg(&d_v[b * 150 + k]) : 0.f;
                u_sp[idx] = (k < 150) ? upi[b * 150 + k] : 0.f;
            }
            __syncthreads();
            int b = tid & 63, jg = tid >> 6;   // 8 j-groups
            const float4* vr4 = (const float4*)(v_sp + b * 156);
            const float4* ur4 = (const float4*)(u_sp + b * 156);
            for (int j = j0g + jg; j < j1g; j += 8) {
                int jl = j - j0g;
                float acc = b_hh[j];
                const float4* wr4 = (const float4*)(sm + WUQ_OFF + jl * 152);
#pragma unroll 19
                for (int q = 0; q < 38; q++) {
                    float4 a4 = vr4[q], w4 = wr4[q];
                    acc += a4.x * w4.x + a4.y * w4.y + a4.z * w4.z + a4.w * w4.w;
                }
                __stcg(&d_gh[b * 450 + j], acc);
            }
            for (int j = j0u + jg; j < j1u; j += 8) {
                int jl = j - j0u;
                float acc = 0.f;
                const float4* wr4 = (const float4*)(sm + WGUG_OFF + jl * 152);
#pragma unroll 19
                for (int q = 0; q < 38; q++) {
                    float4 a4 = ur4[q], w4 = wr4[q];
                    acc += a4.x * w4.x + a4.y * w4.y + a4.z * w4.z + a4.w * w4.w;
                }
                __stcg(&d_gu[b * 600 + j], acc);
            }
        }
        gsync(gen);

        // ---------- Phase B: g = gu + cc@WgC^T ; rg = sig(g)*rbase ----------
        {
            float* c_s = sm + BUF_OFF;   // 64x156 (+pad zeros)
            for (int idx = tid; idx < Bn * 156; idx += NTHR) {
                int b = idx / 156, k = idx - b * 156;
                c_s[idx] = (k < 150) ? __ldcg(&d_cc[b * 150 + k]) : 0.f;
            }
            __syncthreads();
            const int j0 = (blk * 600) >> 7, j1 = ((blk + 1) * 600) >> 7;
            int b = tid & 63, jg = tid >> 6;   // 8 j-groups
            const float4* cr4 = (const float4*)(c_s + b * 156);
            for (int j = j0 + jg; j < j1; j += 8) {
                int jl = j - j0;
                float acc = __ldcg(&d_gu[b * 600 + j]);
                const float4* wc4 = (const float4*)(sm + WGC_OFF + jl * 152);
#pragma unroll 19
                for (int q = 0; q < 38; q++) {
                    float4 a4 = cr4[q], w4 = wc4[q];
                    acc += a4.x * w4.x + a4.y * w4.y + a4.z * w4.z + a4.w * w4.w;
                }
                float sg = fast_sig(acc);
                int km = j % 150;
                float rb = (j < 300) ? __ldg(&Up[i * Bn * 150 + b * 150 + km])
                                     : c_s[b * 156 + km];
                __stcg(&d_rg[b * 600 + j], sg * rb);
            }
        }
        gsync(gen);

        // ---------- Phase C: gi = rg@W_ih^T + b_ih ; GRU combine ----------
        {
            const int half = blk & 1;
            const int hb   = blk >> 1;
            const int b0   = half * 32;
            const int nt   = (hb < 22) ? 3 : 2;
            const int no   = 3 * nt;
            float* rg_s = sm + BUF_OFF;              // 32 rows, 151-f4 stride
            float* part = sm + BUF_OFF + 19400;      // 16 x 288
            float* gi_s = sm + BUF_OFF + 24008;      // 288
            const int tC = tid >> 5, blC = tid & 31;
            const bool act = (tid < 96) && (tC < nt);
            float hr = 0.f, hz = 0.f, hn = 0.f, vold = 0.f;
            int h2 = 0, b2 = 0;
            if (act) {
                h2 = hb + 64 * tC; b2 = b0 + blC;
                hr = __ldcg(&d_gh[b2 * 450 + h2]);
                hz = __ldcg(&d_gh[b2 * 450 + 150 + h2]);
                hn = __ldcg(&d_gh[b2 * 450 + 300 + h2]);
                vold = __ldcg(&d_v[b2 * 150 + h2]);
            }
            const float4* src = (const float4*)(d_rg + b0 * 600);
            float4* rg4 = (float4*)rg_s;
            for (int q = tid; q < 32 * 150; q += NTHR) {
                int bb = q / 150, kq = q - bb * 150;
                rg4[bb * 151 + kq] = __ldcg(&src[bb * 150 + kq]);
            }
            __syncthreads();
            // k-split MMA over 16 warps
            {
                int q0 = (w * 150) >> 4, q1 = ((w + 1) * 150) >> 4;
                const float4* rr  = rg4 + ln * 151;
                const float4* wih = (const float4*)(sm + WIH_OFF);
                if (nt == 3) phaseC_mma<9>(rr, wih, q0, q1, part, w, ln);
                else         phaseC_mma<6>(rr, wih, q0, q1, part, w, ln);
            }
            __syncthreads();
            if (tid < no * 32) {
                int o = tid >> 5;
                float s = 0.f;
#pragma unroll
                for (int ww = 0; ww < 16; ww++) s += part[ww * 288 + tid];
                int t = o / 3, g = o - 3 * t;
                gi_s[tid] = s + __ldg(&b_ih[g * 150 + hb + 64 * t]);
            }
            __syncthreads();
            if (act) {
                float ir  = gi_s[(tC * 3 + 0) * 32 + blC];
                float iz  = gi_s[(tC * 3 + 1) * 32 + blC];
                float in_ = gi_s[(tC * 3 + 2) * 32 + blC];
                float r_ = fast_sig(ir + hr);
                float z_ = fast_sig(iz + hz);
                float n_ = fast_tanh(in_ + r_ * hn);
                float hnew = (1.0f - z_) * n_ + z_ * vold;
                __stcg(&d_v[b2 * 150 + h2], hnew);
                out[(i * Bn + b2) * 150 + h2] = hnew;
            }
        }
        gsync(gen);
    }
}

// ---------------- launch ----------------
extern "C" void kernel_launch(void* const* d_in, const int* in_sizes, int n_in,
                              void* d_out, int out_size)
{
    const float* Up   = (const float*)d_in[0];
    const float* Uq   = (const float*)d_in[1];
    const float* Wp   = (const float*)d_in[2];
    const float* Wq   = (const float*)d_in[3];
    const float* Wv   = (const float*)d_in[4];
    const float* Wg   = (const float*)d_in[5];
    const float* Vm   = (const float*)d_in[6];
    const float* v0   = (const float*)d_in[7];
    const float* W_ih = (const float*)d_in[8];
    const float* W_hh = (const float*)d_in[9];
    const float* b_ih = (const float*)d_in[10];
    const float* b_hh = (const float*)d_in[11];
    float* out = (float*)d_out;

    cudaFuncSetAttribute(pqm_kernel, cudaFuncAttributeMaxDynamicSharedMemorySize, SMEM_BYTES);
    pqm_kernel<<<NBLK, NTHR, SMEM_BYTES>>>(Up, Uq, Wp, Wq, Wv, Wg, Vm, v0,
                                           W_ih, W_hh, b_ih, b_hh, out);
}